// round 1
// baseline (speedup 1.0000x reference)
#include <cuda_runtime.h>
#include <cstdint>

// Problem constants
#define L_LAYERS 4
#define HID      1024
#define NC       256
#define NF       256
#define MB       8192   // batch

// GEMM tiling
#define BM 128
#define BN 128
#define BK 16
#define NTHREADS 256

// -------------------- device scratch (no allocations allowed) --------------------
__device__ float g_Wc  [L_LAYERS * HID * NC];       // 4 MB
__device__ float g_Wu  [L_LAYERS * HID * NF];       // 4 MB
__device__ float g_Wut [L_LAYERS * HID * NF];       // 4 MB
__device__ float g_U   [(L_LAYERS - 1) * HID * HID];// 12 MB
__device__ float g_bias[L_LAYERS * HID];
__device__ float g_u   [MB * HID];                  // 32 MB
__device__ float g_zA  [MB * HID];                  // 32 MB
__device__ float g_zB  [MB * HID];                  // 32 MB

// -------------------- helpers --------------------
__device__ __forceinline__ float softplus_f(float x) {
    // matches jax.nn.softplus: max(x,0) + log1p(exp(-|x|))
    return fmaxf(x, 0.0f) + log1pf(expf(-fabsf(x)));
}

// Apply column-monotone transform: cols 0..3 -> +softplus, 4..7 -> -softplus, else raw.
__global__ void mono_transform_kernel(const float* __restrict__ src,
                                      float* __restrict__ dst,
                                      int total, int rowlen) {
    int idx = blockIdx.x * blockDim.x + threadIdx.x;
    if (idx >= total) return;
    int k = idx % rowlen;
    float x = src[idx];
    if (k < 8) {
        float sp = softplus_f(x);
        x = (k < 4) ? sp : -sp;
    }
    dst[idx] = x;
}

__global__ void softplus_kernel(const float* __restrict__ src,
                                float* __restrict__ dst, int total) {
    int idx = blockIdx.x * blockDim.x + threadIdx.x;
    if (idx >= total) return;
    dst[idx] = softplus_f(src[idx]);
}

__global__ void bias_sum_kernel(const float* __restrict__ a,
                                const float* __restrict__ b,
                                float* __restrict__ dst, int total) {
    int idx = blockIdx.x * blockDim.x + threadIdx.x;
    if (idx >= total) return;
    dst[idx] = a[idx] + b[idx];
}

// -------------------- fused multi-segment GEMM --------------------
// out[m,n] = relu( sum_s X_s[m,:] . W_s[n,:]  + bias[n] + (addend ? addend[m,n] : 0) )
// All X row-major [M,K_s], W row-major [N,K_s] (NT gemm, K contiguous for both).
// M % BM == 0, N % BN == 0, K_s % BK == 0, pointers 16B aligned.
__global__ __launch_bounds__(NTHREADS)
void gemm_relu_kernel(
    const float* __restrict__ X0, const float* __restrict__ W0, int K0,
    const float* __restrict__ X1, const float* __restrict__ W1, int K1,
    const float* __restrict__ X2, const float* __restrict__ W2, int K2,
    const float* __restrict__ bias,
    const float* __restrict__ addend,
    float* __restrict__ out, int M, int N)
{
    __shared__ float Xs[BK][BM + 4];
    __shared__ float Ws[BK][BN + 4];

    const int tid = threadIdx.x;
    const int bm  = blockIdx.y * BM;
    const int bn  = blockIdx.x * BN;
    const int tm  = (tid / 16) * 8;   // 0..120
    const int tn  = (tid % 16) * 8;   // 0..120

    // loader mapping: each thread loads one float4 per row-pass
    const int lr = tid / 4;           // 0..63
    const int lc = (tid % 4) * 4;     // 0,4,8,12

    float acc[8][8];
    #pragma unroll
    for (int i = 0; i < 8; i++)
        #pragma unroll
        for (int j = 0; j < 8; j++) acc[i][j] = 0.0f;

    const float* Xp[3] = {X0, X1, X2};
    const float* Wp[3] = {W0, W1, W2};
    const int    Kp[3] = {K0, K1, K2};

    for (int s = 0; s < 3; ++s) {
        const float* X = Xp[s];
        if (X == nullptr) continue;
        const float* W = Wp[s];
        const int K = Kp[s];

        for (int k0 = 0; k0 < K; k0 += BK) {
            // load 128x16 X tile and 128x16 W tile, transposed to K-major in smem
            #pragma unroll
            for (int h = 0; h < 2; ++h) {
                const int row = lr + h * 64;
                float4 v = *reinterpret_cast<const float4*>(
                    &X[(size_t)(bm + row) * K + k0 + lc]);
                Xs[lc + 0][row] = v.x;
                Xs[lc + 1][row] = v.y;
                Xs[lc + 2][row] = v.z;
                Xs[lc + 3][row] = v.w;
                float4 w = *reinterpret_cast<const float4*>(
                    &W[(size_t)(bn + row) * K + k0 + lc]);
                Ws[lc + 0][row] = w.x;
                Ws[lc + 1][row] = w.y;
                Ws[lc + 2][row] = w.z;
                Ws[lc + 3][row] = w.w;
            }
            __syncthreads();

            #pragma unroll
            for (int k = 0; k < BK; ++k) {
                float a[8], b[8];
                *reinterpret_cast<float4*>(&a[0]) =
                    *reinterpret_cast<const float4*>(&Xs[k][tm]);
                *reinterpret_cast<float4*>(&a[4]) =
                    *reinterpret_cast<const float4*>(&Xs[k][tm + 4]);
                *reinterpret_cast<float4*>(&b[0]) =
                    *reinterpret_cast<const float4*>(&Ws[k][tn]);
                *reinterpret_cast<float4*>(&b[4]) =
                    *reinterpret_cast<const float4*>(&Ws[k][tn + 4]);
                #pragma unroll
                for (int i = 0; i < 8; i++)
                    #pragma unroll
                    for (int j = 0; j < 8; j++)
                        acc[i][j] = fmaf(a[i], b[j], acc[i][j]);
            }
            __syncthreads();
        }
    }

    // epilogue: + bias (+ addend), relu, store
    #pragma unroll
    for (int i = 0; i < 8; i++) {
        const int m = bm + tm + i;
        #pragma unroll
        for (int j = 0; j < 8; j += 4) {
            const int n = bn + tn + j;
            float4 r;
            r.x = acc[i][j + 0];
            r.y = acc[i][j + 1];
            r.z = acc[i][j + 2];
            r.w = acc[i][j + 3];
            float4 bb = *reinterpret_cast<const float4*>(&bias[n]);
            r.x += bb.x; r.y += bb.y; r.z += bb.z; r.w += bb.w;
            if (addend) {
                float4 ad = *reinterpret_cast<const float4*>(
                    &addend[(size_t)m * N + n]);
                r.x += ad.x; r.y += ad.y; r.z += ad.z; r.w += ad.w;
            }
            r.x = fmaxf(r.x, 0.0f);
            r.y = fmaxf(r.y, 0.0f);
            r.z = fmaxf(r.z, 0.0f);
            r.w = fmaxf(r.w, 0.0f);
            *reinterpret_cast<float4*>(&out[(size_t)m * N + n]) = r;
        }
    }
}

// -------------------- launch --------------------
extern "C" void kernel_launch(void* const* d_in, const int* in_sizes, int n_in,
                              void* d_out, int out_size) {
    const float* xc    = (const float*)d_in[0];
    const float* xf    = (const float*)d_in[1];
    const float* Wc_w  = (const float*)d_in[2];
    const float* Wc_b  = (const float*)d_in[3];
    const float* Wu_w  = (const float*)d_in[4];
    const float* Wu_b  = (const float*)d_in[5];
    const float* Wut_w = (const float*)d_in[6];
    const float* Wut_b = (const float*)d_in[7];
    const float* rawU  = (const float*)d_in[8];
    float* out = (float*)d_out;

    float *gWc, *gWu, *gWut, *gU, *gbias, *gu, *gzA, *gzB;
    cudaGetSymbolAddress((void**)&gWc,  g_Wc);
    cudaGetSymbolAddress((void**)&gWu,  g_Wu);
    cudaGetSymbolAddress((void**)&gWut, g_Wut);
    cudaGetSymbolAddress((void**)&gU,   g_U);
    cudaGetSymbolAddress((void**)&gbias,g_bias);
    cudaGetSymbolAddress((void**)&gu,   g_u);
    cudaGetSymbolAddress((void**)&gzA,  g_zA);
    cudaGetSymbolAddress((void**)&gzB,  g_zB);

    // weight transforms (cheap, once per call)
    {
        const int totW = L_LAYERS * HID * NC;
        const int blk = 256;
        mono_transform_kernel<<<(totW + blk - 1) / blk, blk>>>(Wc_w,  gWc,  totW, NC);
        mono_transform_kernel<<<(totW + blk - 1) / blk, blk>>>(Wu_w,  gWu,  totW, NF);
        mono_transform_kernel<<<(totW + blk - 1) / blk, blk>>>(Wut_w, gWut, totW, NF);
        const int totU = (L_LAYERS - 1) * HID * HID;
        softplus_kernel<<<(totU + blk - 1) / blk, blk>>>(rawU, gU, totU);
        const int totB = L_LAYERS * HID;
        bias_sum_kernel<<<(totB + blk - 1) / blk, blk>>>(Wc_b, Wu_b, gbias, totB);
    }

    dim3 grid(HID / BN, MB / BM);   // (8, 64)
    dim3 blk(NTHREADS);

    const float* zprev = nullptr;
    float* zbuf[2] = {gzA, gzB};

    for (int i = 0; i < L_LAYERS; ++i) {
        // u = relu(xf @ Wut_i^T + Wut_b_i)
        gemm_relu_kernel<<<grid, blk>>>(
            xf, gWut + (size_t)i * HID * NF, NF,
            nullptr, nullptr, 0,
            nullptr, nullptr, 0,
            Wut_b + i * HID,
            nullptr,
            gu, MB, HID);

        float* zout = (i == L_LAYERS - 1) ? out : zbuf[i & 1];

        // z = relu(xc@Wc^T + xf@Wu^T [+ z_prev@U^T] + (Wc_b+Wu_b) + u)
        gemm_relu_kernel<<<grid, blk>>>(
            xc, gWc + (size_t)i * HID * NC, NC,
            xf, gWu + (size_t)i * HID * NF, NF,
            (i > 0) ? zprev : nullptr,
            (i > 0) ? (gU + (size_t)(i - 1) * HID * HID) : nullptr,
            (i > 0) ? HID : 0,
            gbias + i * HID,
            gu,
            zout, MB, HID);

        zprev = zout;
    }
}

// round 2
// speedup vs baseline: 3.0798x; 3.0798x over previous
#include <cuda_runtime.h>
#include <cstdint>

// Problem constants
#define L_LAYERS 4
#define HID      1024
#define NC       256
#define NF       256
#define MB       8192   // batch

// GEMM tiling
#define BM 128
#define BN 128
#define BK 32
#define NTHREADS 256
#define SKEW 4

// -------------------- device scratch (no allocations allowed) --------------------
__device__ float g_Wc  [L_LAYERS * HID * NC];
__device__ float g_Wu  [L_LAYERS * HID * NF];
__device__ float g_Wut [L_LAYERS * HID * NF];
__device__ float g_U   [(L_LAYERS - 1) * HID * HID];
__device__ float g_bias[L_LAYERS * HID];
__device__ float g_u   [MB * HID];
__device__ float g_zA  [MB * HID];
__device__ float g_zB  [MB * HID];

// -------------------- helpers --------------------
__device__ __forceinline__ float softplus_f(float x) {
    return fmaxf(x, 0.0f) + log1pf(expf(-fabsf(x)));
}

__device__ __forceinline__ uint32_t f32_to_tf32(float x) {
    uint32_t u;
    asm("cvt.rna.tf32.f32 %0, %1;" : "=r"(u) : "f"(x));
    return u;
}

__global__ void mono_transform_kernel(const float* __restrict__ src,
                                      float* __restrict__ dst,
                                      int total, int rowlen) {
    int idx = blockIdx.x * blockDim.x + threadIdx.x;
    if (idx >= total) return;
    int k = idx % rowlen;
    float x = src[idx];
    if (k < 8) {
        float sp = softplus_f(x);
        x = (k < 4) ? sp : -sp;
    }
    dst[idx] = x;
}

__global__ void softplus_kernel(const float* __restrict__ src,
                                float* __restrict__ dst, int total) {
    int idx = blockIdx.x * blockDim.x + threadIdx.x;
    if (idx >= total) return;
    dst[idx] = softplus_f(src[idx]);
}

__global__ void bias_sum_kernel(const float* __restrict__ a,
                                const float* __restrict__ b,
                                float* __restrict__ dst, int total) {
    int idx = blockIdx.x * blockDim.x + threadIdx.x;
    if (idx >= total) return;
    dst[idx] = a[idx] + b[idx];
}

// -------------------- tf32 tensor-core GEMM --------------------
// out[m,n] = relu( sum_s X_s[m,:] . W_s[n,:] + bias[n] + (addend ? addend[m,n] : 0) )
// X row-major [M,K_s], W row-major [N,K_s] (NT). K_s % BK == 0.
__global__ __launch_bounds__(NTHREADS, 2)
void gemm_tf32_relu_kernel(
    const float* __restrict__ X0, const float* __restrict__ W0, int K0,
    const float* __restrict__ X1, const float* __restrict__ W1, int K1,
    const float* __restrict__ X2, const float* __restrict__ W2, int K2,
    const float* __restrict__ bias,
    const float* __restrict__ addend,
    float* __restrict__ out, int M, int N)
{
    __shared__ uint32_t As[BM][BK + SKEW];
    __shared__ uint32_t Bs[BN][BK + SKEW];

    const int tid  = threadIdx.x;
    const int lane = tid & 31;
    const int wid  = tid >> 5;
    const int wm   = wid & 3;   // 4 warps along M, 32 rows each
    const int wn   = wid >> 2;  // 2 warps along N, 64 cols each
    const int bm   = blockIdx.y * BM;
    const int bn   = blockIdx.x * BN;

    const int lk = lane & 3;    // 0..3
    const int lr = lane >> 2;   // 0..7

    // acc[mi][ni][4]: mi in 0..1 (16-row frags), ni in 0..7 (8-col frags)
    float acc[2][8][4];
    #pragma unroll
    for (int mi = 0; mi < 2; mi++)
        #pragma unroll
        for (int ni = 0; ni < 8; ni++)
            #pragma unroll
            for (int t = 0; t < 4; t++) acc[mi][ni][t] = 0.0f;

    const float* Xp[3] = {X0, X1, X2};
    const float* Wp[3] = {W0, W1, W2};
    const int    Kp[3] = {K0, K1, K2};

    for (int s = 0; s < 3; ++s) {
        const float* X = Xp[s];
        if (X == nullptr) continue;
        const float* W = Wp[s];
        const int K = Kp[s];

        for (int k0 = 0; k0 < K; k0 += BK) {
            // -------- load 128x32 X and W tiles, convert to tf32 --------
            #pragma unroll
            for (int j = 0; j < 4; ++j) {
                const int f    = tid + NTHREADS * j;
                const int row  = f >> 3;
                const int col4 = (f & 7) << 2;
                float4 v = *reinterpret_cast<const float4*>(
                    &X[(size_t)(bm + row) * K + k0 + col4]);
                As[row][col4 + 0] = f32_to_tf32(v.x);
                As[row][col4 + 1] = f32_to_tf32(v.y);
                As[row][col4 + 2] = f32_to_tf32(v.z);
                As[row][col4 + 3] = f32_to_tf32(v.w);
                float4 w = *reinterpret_cast<const float4*>(
                    &W[(size_t)(bn + row) * K + k0 + col4]);
                Bs[row][col4 + 0] = f32_to_tf32(w.x);
                Bs[row][col4 + 1] = f32_to_tf32(w.y);
                Bs[row][col4 + 2] = f32_to_tf32(w.z);
                Bs[row][col4 + 3] = f32_to_tf32(w.w);
            }
            __syncthreads();

            // -------- 4 k-steps of m16n8k8 --------
            #pragma unroll
            for (int kk = 0; kk < BK; kk += 8) {
                uint32_t a[2][4];
                uint32_t b[8][2];
                #pragma unroll
                for (int mi = 0; mi < 2; mi++) {
                    const int r = wm * 32 + mi * 16 + lr;
                    a[mi][0] = As[r    ][kk + lk    ];
                    a[mi][1] = As[r + 8][kk + lk    ];
                    a[mi][2] = As[r    ][kk + lk + 4];
                    a[mi][3] = As[r + 8][kk + lk + 4];
                }
                #pragma unroll
                for (int ni = 0; ni < 8; ni++) {
                    const int c = wn * 64 + ni * 8 + lr;
                    b[ni][0] = Bs[c][kk + lk    ];
                    b[ni][1] = Bs[c][kk + lk + 4];
                }
                #pragma unroll
                for (int mi = 0; mi < 2; mi++) {
                    #pragma unroll
                    for (int ni = 0; ni < 8; ni++) {
                        asm volatile(
                            "mma.sync.aligned.m16n8k8.row.col.f32.tf32.tf32.f32 "
                            "{%0,%1,%2,%3}, {%4,%5,%6,%7}, {%8,%9}, {%0,%1,%2,%3};"
                            : "+f"(acc[mi][ni][0]), "+f"(acc[mi][ni][1]),
                              "+f"(acc[mi][ni][2]), "+f"(acc[mi][ni][3])
                            : "r"(a[mi][0]), "r"(a[mi][1]),
                              "r"(a[mi][2]), "r"(a[mi][3]),
                              "r"(b[ni][0]), "r"(b[ni][1]));
                    }
                }
            }
            __syncthreads();
        }
    }

    // -------- epilogue: + bias (+ addend), relu, store --------
    const int lc2 = (lane & 3) * 2;
    #pragma unroll
    for (int mi = 0; mi < 2; mi++) {
        const int r0 = bm + wm * 32 + mi * 16 + lr;
        const int r1 = r0 + 8;
        #pragma unroll
        for (int ni = 0; ni < 8; ni++) {
            const int c = bn + wn * 64 + ni * 8 + lc2;
            float2 bb = *reinterpret_cast<const float2*>(&bias[c]);
            float v0 = acc[mi][ni][0] + bb.x;
            float v1 = acc[mi][ni][1] + bb.y;
            float v2 = acc[mi][ni][2] + bb.x;
            float v3 = acc[mi][ni][3] + bb.y;
            if (addend) {
                float2 a0 = *reinterpret_cast<const float2*>(
                    &addend[(size_t)r0 * N + c]);
                float2 a1 = *reinterpret_cast<const float2*>(
                    &addend[(size_t)r1 * N + c]);
                v0 += a0.x; v1 += a0.y;
                v2 += a1.x; v3 += a1.y;
            }
            float2 o0, o1;
            o0.x = fmaxf(v0, 0.0f); o0.y = fmaxf(v1, 0.0f);
            o1.x = fmaxf(v2, 0.0f); o1.y = fmaxf(v3, 0.0f);
            *reinterpret_cast<float2*>(&out[(size_t)r0 * N + c]) = o0;
            *reinterpret_cast<float2*>(&out[(size_t)r1 * N + c]) = o1;
        }
    }
}

// -------------------- launch --------------------
extern "C" void kernel_launch(void* const* d_in, const int* in_sizes, int n_in,
                              void* d_out, int out_size) {
    const float* xc    = (const float*)d_in[0];
    const float* xf    = (const float*)d_in[1];
    const float* Wc_w  = (const float*)d_in[2];
    const float* Wc_b  = (const float*)d_in[3];
    const float* Wu_w  = (const float*)d_in[4];
    const float* Wu_b  = (const float*)d_in[5];
    const float* Wut_w = (const float*)d_in[6];
    const float* Wut_b = (const float*)d_in[7];
    const float* rawU  = (const float*)d_in[8];
    float* out = (float*)d_out;

    float *gWc, *gWu, *gWut, *gU, *gbias, *gu, *gzA, *gzB;
    cudaGetSymbolAddress((void**)&gWc,  g_Wc);
    cudaGetSymbolAddress((void**)&gWu,  g_Wu);
    cudaGetSymbolAddress((void**)&gWut, g_Wut);
    cudaGetSymbolAddress((void**)&gU,   g_U);
    cudaGetSymbolAddress((void**)&gbias,g_bias);
    cudaGetSymbolAddress((void**)&gu,   g_u);
    cudaGetSymbolAddress((void**)&gzA,  g_zA);
    cudaGetSymbolAddress((void**)&gzB,  g_zB);

    // weight transforms (cheap, once per call)
    {
        const int totW = L_LAYERS * HID * NC;
        const int blk = 256;
        mono_transform_kernel<<<(totW + blk - 1) / blk, blk>>>(Wc_w,  gWc,  totW, NC);
        mono_transform_kernel<<<(totW + blk - 1) / blk, blk>>>(Wu_w,  gWu,  totW, NF);
        mono_transform_kernel<<<(totW + blk - 1) / blk, blk>>>(Wut_w, gWut, totW, NF);
        const int totU = (L_LAYERS - 1) * HID * HID;
        softplus_kernel<<<(totU + blk - 1) / blk, blk>>>(rawU, gU, totU);
        const int totB = L_LAYERS * HID;
        bias_sum_kernel<<<(totB + blk - 1) / blk, blk>>>(Wc_b, Wu_b, gbias, totB);
    }

    dim3 grid(HID / BN, MB / BM);   // (8, 64)
    dim3 blk(NTHREADS);

    const float* zprev = nullptr;
    float* zbuf[2] = {gzA, gzB};

    for (int i = 0; i < L_LAYERS; ++i) {
        // u = relu(xf @ Wut_i^T + Wut_b_i)
        gemm_tf32_relu_kernel<<<grid, blk>>>(
            xf, gWut + (size_t)i * HID * NF, NF,
            nullptr, nullptr, 0,
            nullptr, nullptr, 0,
            Wut_b + i * HID,
            nullptr,
            gu, MB, HID);

        float* zout = (i == L_LAYERS - 1) ? out : zbuf[i & 1];

        // z = relu(xc@Wc^T + xf@Wu^T [+ z_prev@U^T] + (Wc_b+Wu_b) + u)
        gemm_tf32_relu_kernel<<<grid, blk>>>(
            xc, gWc + (size_t)i * HID * NC, NC,
            xf, gWu + (size_t)i * HID * NF, NF,
            (i > 0) ? zprev : nullptr,
            (i > 0) ? (gU + (size_t)(i - 1) * HID * HID) : nullptr,
            (i > 0) ? HID : 0,
            gbias + i * HID,
            gu,
            zout, MB, HID);

        zprev = zout;
    }
}

// round 5
// speedup vs baseline: 6.6539x; 2.1605x over previous
#include <cuda_runtime.h>
#include <cuda_fp16.h>
#include <cstdint>

// ---------------- problem constants ----------------
#define L_LAYERS 4
#define HID      1024
#define NC       256
#define NF       256
#define MB       8192
#define KCAT     512

#define ZSCALE     0.0009765625f   // 2^-10, z storage scale
#define USCALE_INV 1024.0f         // U pre-scaled by 2^10

// ---------------- GEMM tiling ----------------
#define BM 128
#define BN 128
#define BKH 64                 // K per tile, in halfs (128 bytes)
#define STAGES 3
#define NTHREADS 256

#define ROW_BYTES 144          // 64 halfs * 2B + 16B pad (conflict-free)
#define TILE_BYTES (128 * ROW_BYTES)
#define STAGE_BYTES (2 * TILE_BYTES)
#define SMEM_BYTES (STAGES * STAGE_BYTES)     // 110592

// ---------------- device scratch ----------------
__device__ __half g_Wcat[L_LAYERS * HID * KCAT];
__device__ __half g_Wut [L_LAYERS * HID * NF];
__device__ __half g_U   [(L_LAYERS - 1) * HID * HID];   // softplus(U) * 2^10
__device__ float  g_bias[L_LAYERS * HID];
__device__ __half g_Xcat[MB * KCAT];
__device__ __half g_zA  [MB * HID];                     // z * 2^-10
__device__ __half g_zB  [MB * HID];

// ---------------- helpers ----------------
__device__ __forceinline__ float softplus_f(float x) {
    return fmaxf(x, 0.0f) + log1pf(expf(-fabsf(x)));
}
__device__ __forceinline__ void cp_async16(uint32_t dst, const void* src) {
    asm volatile("cp.async.cg.shared.global [%0], [%1], 16;"
                 :: "r"(dst), "l"(src) : "memory");
}
__device__ __forceinline__ uint32_t smem_u32(const void* p) {
    uint32_t a;
    asm("{ .reg .u64 t; cvta.to.shared.u64 t, %1; cvt.u32.u64 %0, t; }"
        : "=r"(a) : "l"(p));
    return a;
}

// ---------------- prep kernels ----------------
#define WSEG (L_LAYERS * HID * 256)
#define USEG ((L_LAYERS - 1) * HID * HID)

__global__ void prep_weights_kernel(const float* __restrict__ Wc_w,
                                    const float* __restrict__ Wu_w,
                                    const float* __restrict__ Wut_w,
                                    const float* __restrict__ rawU,
                                    const float* __restrict__ Wc_b,
                                    const float* __restrict__ Wu_b) {
    int idx = blockIdx.x * blockDim.x + threadIdx.x;
    if (idx < WSEG) {                       // Wc -> Wcat cols [0,256)
        int r = idx >> 8, k = idx & 255;
        float x = Wc_w[idx];
        if (k < 8) { float sp = softplus_f(x); x = (k < 4) ? sp : -sp; }
        g_Wcat[(size_t)r * KCAT + k] = __float2half_rn(x);
        return;
    }
    idx -= WSEG;
    if (idx < WSEG) {                       // Wu -> Wcat cols [256,512)
        int r = idx >> 8, k = idx & 255;
        float x = Wu_w[idx];
        if (k < 8) { float sp = softplus_f(x); x = (k < 4) ? sp : -sp; }
        g_Wcat[(size_t)r * KCAT + 256 + k] = __float2half_rn(x);
        return;
    }
    idx -= WSEG;
    if (idx < WSEG) {                       // Wut
        int k = idx & 255;
        float x = Wut_w[idx];
        if (k < 8) { float sp = softplus_f(x); x = (k < 4) ? sp : -sp; }
        g_Wut[idx] = __float2half_rn(x);
        return;
    }
    idx -= WSEG;
    if (idx < USEG) {                       // U = softplus(rawU) * 2^10
        g_U[idx] = __float2half_rn(softplus_f(rawU[idx]) * USCALE_INV);
        return;
    }
    idx -= USEG;
    if (idx < L_LAYERS * HID) {
        g_bias[idx] = Wc_b[idx] + Wu_b[idx];
    }
}

__global__ void xcat_kernel(const float* __restrict__ xc,
                            const float* __restrict__ xf) {
    int idx = blockIdx.x * blockDim.x + threadIdx.x;
    if (idx >= MB * KCAT) return;
    int row = idx >> 9, col = idx & 511;
    float v = (col < 256) ? xc[row * 256 + col] : xf[row * 256 + (col - 256)];
    g_Xcat[idx] = __float2half_rn(v);
}

// ---------------- fused per-layer GEMM ----------------
// Phase 1 (tiles [0, tU)):       acc  = xf @ Wut^T          then acc = relu(acc + bias_u)
// Phase 2 (tiles [tU, T)):       acc += Xcat @ Wcat^T  + zprev @ Uscaled^T
// Final: out = relu(acc + bias_z); store fp16*2^-10 (mid layers) or fp32 (last).
struct SegSrc { const __half* X; int ldx; const __half* W; int ldw; int k0; };

__device__ __forceinline__ SegSrc seg_src(int t, int tU, int t1,
    const __half* Xu, const __half* Wut,
    const __half* Xc, const __half* Wc,
    const __half* Zp, const __half* U) {
    SegSrc s;
    if (t < tU)            { s.X = Xu; s.ldx = KCAT; s.W = Wut; s.ldw = NF;   s.k0 = t * BKH; }
    else if (t < tU + 8)   { s.X = Xc; s.ldx = KCAT; s.W = Wc;  s.ldw = KCAT; s.k0 = (t - tU) * BKH; }
    else                   { s.X = Zp; s.ldx = HID;  s.W = U;   s.ldw = HID;  s.k0 = (t - tU - 8) * BKH; }
    return s;
}

__device__ __forceinline__ void load_tile_f16(uint32_t sA, uint32_t sB,
                                              const SegSrc s, int bm, int bn, int tid) {
    #pragma unroll
    for (int j = 0; j < 4; j++) {
        const int f = tid + NTHREADS * j;
        const int row = f >> 3, c = f & 7;
        cp_async16(sA + row * ROW_BYTES + c * 16,
                   s.X + (size_t)(bm + row) * s.ldx + s.k0 + c * 8);
        cp_async16(sB + row * ROW_BYTES + c * 16,
                   s.W + (size_t)(bn + row) * s.ldw + s.k0 + c * 8);
    }
    asm volatile("cp.async.commit_group;" ::: "memory");
}

__global__ void __launch_bounds__(NTHREADS, 2)
icnn_layer_f16(const __half* __restrict__ Xcat,
               const __half* __restrict__ Wut,     // layer's Wut
               const __half* __restrict__ Wcat,    // layer's [Wc|Wu]
               const __half* __restrict__ Zprev,   // scaled z, or null (layer 0)
               const __half* __restrict__ U,       // scaled U, or null
               const float* __restrict__ bias_u,   // Wut_b
               const float* __restrict__ bias_z,   // Wc_b + Wu_b
               float* __restrict__ outF,           // last layer
               __half* __restrict__ outH)          // mid layers (scaled)
{
    extern __shared__ __align__(16) char dsm[];
    const uint32_t sbase = smem_u32(dsm);

    const int tid  = threadIdx.x;
    const int lane = tid & 31;
    const int wid  = tid >> 5;
    const int wm   = wid & 3;
    const int wn   = wid >> 2;
    const int lk   = lane & 3;
    const int lr   = lane >> 2;
    const int bn   = blockIdx.x * BN;
    const int bm   = blockIdx.y * BM;

    const __half* Xu = Xcat + 256;   // xf columns
    const int tU = NF / BKH;         // 4
    const int t1 = Zprev ? (HID / BKH) : 0;
    const int T  = tU + KCAT / BKH + t1;

    // preload biases for this thread's columns
    float2 bu[8], bz[8];
    #pragma unroll
    for (int ni = 0; ni < 8; ni++) {
        const int c = bn + wn * 64 + ni * 8 + lk * 2;
        bu[ni] = *reinterpret_cast<const float2*>(&bias_u[c]);
        bz[ni] = *reinterpret_cast<const float2*>(&bias_z[c]);
    }

    float acc[2][8][4];
    #pragma unroll
    for (int mi = 0; mi < 2; mi++)
        #pragma unroll
        for (int ni = 0; ni < 8; ni++)
            #pragma unroll
            for (int q = 0; q < 4; q++) acc[mi][ni][q] = 0.0f;

    // prologue
    #pragma unroll
    for (int p = 0; p < STAGES - 1; p++) {
        SegSrc s = seg_src(p, tU, t1, Xu, Wut, Xcat, Wcat, Zprev, U);
        load_tile_f16(sbase + p * STAGE_BYTES,
                      sbase + p * STAGE_BYTES + TILE_BYTES, s, bm, bn, tid);
    }

    for (int t = 0; t < T; t++) {
        // phase boundary: u = relu(u_acc + bias_u), then keep accumulating
        if (t == tU) {
            #pragma unroll
            for (int mi = 0; mi < 2; mi++)
                #pragma unroll
                for (int ni = 0; ni < 8; ni++) {
                    acc[mi][ni][0] = fmaxf(acc[mi][ni][0] + bu[ni].x, 0.0f);
                    acc[mi][ni][1] = fmaxf(acc[mi][ni][1] + bu[ni].y, 0.0f);
                    acc[mi][ni][2] = fmaxf(acc[mi][ni][2] + bu[ni].x, 0.0f);
                    acc[mi][ni][3] = fmaxf(acc[mi][ni][3] + bu[ni].y, 0.0f);
                }
        }

        if (t < T - 1) asm volatile("cp.async.wait_group 1;" ::: "memory");
        else           asm volatile("cp.async.wait_group 0;" ::: "memory");
        __syncthreads();

        const int pf = t + STAGES - 1;
        if (pf < T) {
            SegSrc s = seg_src(pf, tU, t1, Xu, Wut, Xcat, Wcat, Zprev, U);
            const int ps = pf % STAGES;
            load_tile_f16(sbase + ps * STAGE_BYTES,
                          sbase + ps * STAGE_BYTES + TILE_BYTES, s, bm, bn, tid);
        }

        const char* sA = dsm + (t % STAGES) * STAGE_BYTES;
        const char* sB = sA + TILE_BYTES;

        #pragma unroll
        for (int kk = 0; kk < BKH; kk += 16) {
            uint32_t a[2][4], b[8][2];
            #pragma unroll
            for (int mi = 0; mi < 2; mi++) {
                const int r = wm * 32 + mi * 16 + lr;
                const int base = r * ROW_BYTES + kk * 2 + lk * 4;
                a[mi][0] = *(const uint32_t*)(sA + base);
                a[mi][1] = *(const uint32_t*)(sA + base + 8 * ROW_BYTES);
                a[mi][2] = *(const uint32_t*)(sA + base + 16);
                a[mi][3] = *(const uint32_t*)(sA + base + 8 * ROW_BYTES + 16);
            }
            #pragma unroll
            for (int ni = 0; ni < 8; ni++) {
                const int n = wn * 64 + ni * 8 + lr;
                const int base = n * ROW_BYTES + kk * 2 + lk * 4;
                b[ni][0] = *(const uint32_t*)(sB + base);
                b[ni][1] = *(const uint32_t*)(sB + base + 16);
            }
            #pragma unroll
            for (int mi = 0; mi < 2; mi++) {
                #pragma unroll
                for (int ni = 0; ni < 8; ni++) {
                    asm volatile(
                        "mma.sync.aligned.m16n8k16.row.col.f32.f16.f16.f32 "
                        "{%0,%1,%2,%3}, {%4,%5,%6,%7}, {%8,%9}, {%0,%1,%2,%3};"
                        : "+f"(acc[mi][ni][0]), "+f"(acc[mi][ni][1]),
                          "+f"(acc[mi][ni][2]), "+f"(acc[mi][ni][3])
                        : "r"(a[mi][0]), "r"(a[mi][1]),
                          "r"(a[mi][2]), "r"(a[mi][3]),
                          "r"(b[ni][0]), "r"(b[ni][1]));
                }
            }
        }
        __syncthreads();
    }

    // -------- final epilogue: z = relu(acc + bias_z) --------
    #pragma unroll
    for (int mi = 0; mi < 2; mi++) {
        const int r0 = bm + wm * 32 + mi * 16 + lr;
        const int r1 = r0 + 8;
        #pragma unroll
        for (int ni = 0; ni < 8; ni++) {
            const int c = bn + wn * 64 + ni * 8 + lk * 2;
            float v0 = fmaxf(acc[mi][ni][0] + bz[ni].x, 0.0f);
            float v1 = fmaxf(acc[mi][ni][1] + bz[ni].y, 0.0f);
            float v2 = fmaxf(acc[mi][ni][2] + bz[ni].x, 0.0f);
            float v3 = fmaxf(acc[mi][ni][3] + bz[ni].y, 0.0f);
            if (outH) {
                *reinterpret_cast<__half2*>(&outH[(size_t)r0 * HID + c]) =
                    __floats2half2_rn(v0 * ZSCALE, v1 * ZSCALE);
                *reinterpret_cast<__half2*>(&outH[(size_t)r1 * HID + c]) =
                    __floats2half2_rn(v2 * ZSCALE, v3 * ZSCALE);
            } else {
                *reinterpret_cast<float2*>(&outF[(size_t)r0 * HID + c]) =
                    make_float2(v0, v1);
                *reinterpret_cast<float2*>(&outF[(size_t)r1 * HID + c]) =
                    make_float2(v2, v3);
            }
        }
    }
}

// ---------------- launch ----------------
extern "C" void kernel_launch(void* const* d_in, const int* in_sizes, int n_in,
                              void* d_out, int out_size) {
    const float* xc    = (const float*)d_in[0];
    const float* xf    = (const float*)d_in[1];
    const float* Wc_w  = (const float*)d_in[2];
    const float* Wc_b  = (const float*)d_in[3];
    const float* Wu_w  = (const float*)d_in[4];
    const float* Wu_b  = (const float*)d_in[5];
    const float* Wut_w = (const float*)d_in[6];
    const float* Wut_b = (const float*)d_in[7];
    const float* rawU  = (const float*)d_in[8];
    float* out = (float*)d_out;

    __half *gWcat, *gWut, *gU, *gXcat, *gzA, *gzB;
    float *gbias;
    cudaGetSymbolAddress((void**)&gWcat, g_Wcat);
    cudaGetSymbolAddress((void**)&gWut,  g_Wut);
    cudaGetSymbolAddress((void**)&gU,    g_U);
    cudaGetSymbolAddress((void**)&gbias, g_bias);
    cudaGetSymbolAddress((void**)&gXcat, g_Xcat);
    cudaGetSymbolAddress((void**)&gzA,   g_zA);
    cudaGetSymbolAddress((void**)&gzB,   g_zB);

    cudaFuncSetAttribute(icnn_layer_f16,
                         cudaFuncAttributeMaxDynamicSharedMemorySize, SMEM_BYTES);

    {
        const int totP = 3 * WSEG + USEG + L_LAYERS * HID;
        prep_weights_kernel<<<(totP + 255) / 256, 256>>>(Wc_w, Wu_w, Wut_w,
                                                         rawU, Wc_b, Wu_b);
        const int totX = MB * KCAT;
        xcat_kernel<<<(totX + 255) / 256, 256>>>(xc, xf);
    }

    dim3 grid(HID / BN, MB / BM);   // (8, 64)
    dim3 blk(NTHREADS);

    const __half* zprev = nullptr;
    __half* zbuf[2] = {gzA, gzB};

    for (int i = 0; i < L_LAYERS; ++i) {
        const bool last = (i == L_LAYERS - 1);
        icnn_layer_f16<<<grid, blk, SMEM_BYTES>>>(
            gXcat,
            gWut + (size_t)i * HID * NF,
            gWcat + (size_t)i * HID * KCAT,
            zprev,
            (i > 0) ? (gU + (size_t)(i - 1) * HID * HID) : nullptr,
            Wut_b + i * HID,
            gbias + i * HID,
            last ? out : nullptr,
            last ? nullptr : zbuf[i & 1]);
        zprev = zbuf[i & 1];
    }
}

// round 6
// speedup vs baseline: 7.3224x; 1.1005x over previous
#include <cuda_runtime.h>
#include <cuda_fp16.h>
#include <cstdint>

// ---------------- problem constants ----------------
#define L_LAYERS 4
#define HID      1024
#define NC       256
#define NF       256
#define MB       8192
#define KCAT     512

#define ZSCALE     0.0009765625f   // 2^-10, z storage scale
#define USCALE_INV 1024.0f         // U pre-scaled by 2^10

// ---------------- GEMM tiling ----------------
#define BM 128
#define BN 128
#define BKH 64                 // K per tile, in halfs (128 bytes)
#define STAGES 3
#define NTHREADS 256

#define ROW_BYTES 144          // 64 halfs * 2B + 16B pad (conflict-free for ldmatrix)
#define TILE_BYTES (128 * ROW_BYTES)
#define STAGE_BYTES (2 * TILE_BYTES)
#define SMEM_BYTES (STAGES * STAGE_BYTES)     // 110592

// ---------------- device scratch ----------------
__device__ __half g_Wcat[L_LAYERS * HID * KCAT];
__device__ __half g_Wut [L_LAYERS * HID * NF];
__device__ __half g_U   [(L_LAYERS - 1) * HID * HID];   // softplus(U) * 2^10
__device__ float  g_bias[L_LAYERS * HID];
__device__ __half g_Xcat[MB * KCAT];
__device__ __half g_zA  [MB * HID];                     // z * 2^-10
__device__ __half g_zB  [MB * HID];

// ---------------- helpers ----------------
__device__ __forceinline__ float softplus_f(float x) {
    return fmaxf(x, 0.0f) + log1pf(expf(-fabsf(x)));
}
__device__ __forceinline__ void cp_async16(uint32_t dst, const void* src) {
    asm volatile("cp.async.cg.shared.global [%0], [%1], 16;"
                 :: "r"(dst), "l"(src) : "memory");
}
__device__ __forceinline__ uint32_t smem_u32(const void* p) {
    uint32_t a;
    asm("{ .reg .u64 t; cvta.to.shared.u64 t, %1; cvt.u32.u64 %0, t; }"
        : "=r"(a) : "l"(p));
    return a;
}
__device__ __forceinline__ void ldmatrix_x4(uint32_t& r0, uint32_t& r1,
                                            uint32_t& r2, uint32_t& r3,
                                            uint32_t addr) {
    asm volatile("ldmatrix.sync.aligned.m8n8.x4.shared.b16 {%0,%1,%2,%3}, [%4];"
                 : "=r"(r0), "=r"(r1), "=r"(r2), "=r"(r3) : "r"(addr));
}

// ---------------- prep kernels ----------------
#define WSEG (L_LAYERS * HID * 256)
#define USEG ((L_LAYERS - 1) * HID * HID)

__global__ void prep_weights_kernel(const float* __restrict__ Wc_w,
                                    const float* __restrict__ Wu_w,
                                    const float* __restrict__ Wut_w,
                                    const float* __restrict__ rawU,
                                    const float* __restrict__ Wc_b,
                                    const float* __restrict__ Wu_b) {
    int idx = blockIdx.x * blockDim.x + threadIdx.x;
    if (idx < WSEG) {
        int r = idx >> 8, k = idx & 255;
        float x = Wc_w[idx];
        if (k < 8) { float sp = softplus_f(x); x = (k < 4) ? sp : -sp; }
        g_Wcat[(size_t)r * KCAT + k] = __float2half_rn(x);
        return;
    }
    idx -= WSEG;
    if (idx < WSEG) {
        int r = idx >> 8, k = idx & 255;
        float x = Wu_w[idx];
        if (k < 8) { float sp = softplus_f(x); x = (k < 4) ? sp : -sp; }
        g_Wcat[(size_t)r * KCAT + 256 + k] = __float2half_rn(x);
        return;
    }
    idx -= WSEG;
    if (idx < WSEG) {
        int k = idx & 255;
        float x = Wut_w[idx];
        if (k < 8) { float sp = softplus_f(x); x = (k < 4) ? sp : -sp; }
        g_Wut[idx] = __float2half_rn(x);
        return;
    }
    idx -= WSEG;
    if (idx < USEG) {
        g_U[idx] = __float2half_rn(softplus_f(rawU[idx]) * USCALE_INV);
        return;
    }
    idx -= USEG;
    if (idx < L_LAYERS * HID) {
        g_bias[idx] = Wc_b[idx] + Wu_b[idx];
    }
}

__global__ void xcat_kernel(const float* __restrict__ xc,
                            const float* __restrict__ xf) {
    int idx = blockIdx.x * blockDim.x + threadIdx.x;
    if (idx >= MB * KCAT) return;
    int row = idx >> 9, col = idx & 511;
    float v = (col < 256) ? xc[row * 256 + col] : xf[row * 256 + (col - 256)];
    g_Xcat[idx] = __float2half_rn(v);
}

// ---------------- fused per-layer GEMM ----------------
struct SegSrc { const __half* X; int ldx; const __half* W; int ldw; int k0; };

__device__ __forceinline__ SegSrc seg_src(int t, int tU,
    const __half* Xu, const __half* Wut,
    const __half* Xc, const __half* Wc,
    const __half* Zp, const __half* U) {
    SegSrc s;
    if (t < tU)            { s.X = Xu; s.ldx = KCAT; s.W = Wut; s.ldw = NF;   s.k0 = t * BKH; }
    else if (t < tU + 8)   { s.X = Xc; s.ldx = KCAT; s.W = Wc;  s.ldw = KCAT; s.k0 = (t - tU) * BKH; }
    else                   { s.X = Zp; s.ldx = HID;  s.W = U;   s.ldw = HID;  s.k0 = (t - tU - 8) * BKH; }
    return s;
}

__device__ __forceinline__ void load_tile_f16(uint32_t sA, uint32_t sB,
                                              const SegSrc s, int bm, int bn, int tid) {
    #pragma unroll
    for (int j = 0; j < 4; j++) {
        const int f = tid + NTHREADS * j;
        const int row = f >> 3, c = f & 7;
        cp_async16(sA + row * ROW_BYTES + c * 16,
                   s.X + (size_t)(bm + row) * s.ldx + s.k0 + c * 8);
        cp_async16(sB + row * ROW_BYTES + c * 16,
                   s.W + (size_t)(bn + row) * s.ldw + s.k0 + c * 8);
    }
    asm volatile("cp.async.commit_group;" ::: "memory");
}

__global__ void __launch_bounds__(NTHREADS, 2)
icnn_layer_f16(const __half* __restrict__ Xcat,
               const __half* __restrict__ Wut,
               const __half* __restrict__ Wcat,
               const __half* __restrict__ Zprev,
               const __half* __restrict__ U,
               const float* __restrict__ bias_u,
               const float* __restrict__ bias_z,
               float* __restrict__ outF,
               __half* __restrict__ outH)
{
    extern __shared__ __align__(16) char dsm[];
    const uint32_t sbase = smem_u32(dsm);

    const int tid  = threadIdx.x;
    const int lane = tid & 31;
    const int wid  = tid >> 5;
    const int wm   = wid & 3;
    const int wn   = wid >> 2;
    const int lk   = lane & 3;
    const int lr   = lane >> 2;
    const int bn   = blockIdx.x * BN;
    const int bm   = blockIdx.y * BM;

    const __half* Xu = Xcat + 256;
    const int tU = NF / BKH;         // 4
    const int t1 = Zprev ? (HID / BKH) : 0;
    const int T  = tU + KCAT / BKH + t1;

    // ldmatrix per-lane row offsets (loop-invariant)
    // A frags: mi in {0,1}: 16 rows starting at wm*32+mi*16; groups 2,3 are +16B in k
    uint32_t aOff[2];
    #pragma unroll
    for (int mi = 0; mi < 2; mi++) {
        const int row = wm * 32 + mi * 16 + (lane & 15);
        aOff[mi] = row * ROW_BYTES + ((lane >> 4) << 4);
    }
    // B frags: ni2 in 0..3 covers n-tiles 2*ni2, 2*ni2+1 (16 n-rows), k split by bit3
    uint32_t bOff[4];
    #pragma unroll
    for (int ni2 = 0; ni2 < 4; ni2++) {
        const int n = wn * 64 + ni2 * 16 + (lane & 7) + ((lane >> 4) << 3);
        bOff[ni2] = n * ROW_BYTES + (((lane >> 3) & 1) << 4);
    }

    // preload biases
    float2 bu[8], bz[8];
    #pragma unroll
    for (int ni = 0; ni < 8; ni++) {
        const int c = bn + wn * 64 + ni * 8 + lk * 2;
        bu[ni] = *reinterpret_cast<const float2*>(&bias_u[c]);
        bz[ni] = *reinterpret_cast<const float2*>(&bias_z[c]);
    }

    float acc[2][8][4];
    #pragma unroll
    for (int mi = 0; mi < 2; mi++)
        #pragma unroll
        for (int ni = 0; ni < 8; ni++)
            #pragma unroll
            for (int q = 0; q < 4; q++) acc[mi][ni][q] = 0.0f;

    // prologue
    #pragma unroll
    for (int p = 0; p < STAGES - 1; p++) {
        SegSrc s = seg_src(p, tU, Xu, Wut, Xcat, Wcat, Zprev, U);
        load_tile_f16(sbase + p * STAGE_BYTES,
                      sbase + p * STAGE_BYTES + TILE_BYTES, s, bm, bn, tid);
    }

    for (int t = 0; t < T; t++) {
        if (t == tU) {   // phase boundary: u = relu(u_acc + bias_u)
            #pragma unroll
            for (int mi = 0; mi < 2; mi++)
                #pragma unroll
                for (int ni = 0; ni < 8; ni++) {
                    acc[mi][ni][0] = fmaxf(acc[mi][ni][0] + bu[ni].x, 0.0f);
                    acc[mi][ni][1] = fmaxf(acc[mi][ni][1] + bu[ni].y, 0.0f);
                    acc[mi][ni][2] = fmaxf(acc[mi][ni][2] + bu[ni].x, 0.0f);
                    acc[mi][ni][3] = fmaxf(acc[mi][ni][3] + bu[ni].y, 0.0f);
                }
        }

        if (t < T - 1) asm volatile("cp.async.wait_group 1;" ::: "memory");
        else           asm volatile("cp.async.wait_group 0;" ::: "memory");
        __syncthreads();

        const int pf = t + STAGES - 1;
        if (pf < T) {
            SegSrc s = seg_src(pf, tU, Xu, Wut, Xcat, Wcat, Zprev, U);
            const int ps = pf % STAGES;
            load_tile_f16(sbase + ps * STAGE_BYTES,
                          sbase + ps * STAGE_BYTES + TILE_BYTES, s, bm, bn, tid);
        }

        const uint32_t stA = sbase + (t % STAGES) * STAGE_BYTES;
        const uint32_t stB = stA + TILE_BYTES;

        #pragma unroll
        for (int kk = 0; kk < BKH; kk += 16) {
            uint32_t a[2][4], b[8][2];
            #pragma unroll
            for (int mi = 0; mi < 2; mi++)
                ldmatrix_x4(a[mi][0], a[mi][1], a[mi][2], a[mi][3],
                            stA + aOff[mi] + kk * 2);
            #pragma unroll
            for (int ni2 = 0; ni2 < 4; ni2++)
                ldmatrix_x4(b[2*ni2][0], b[2*ni2][1], b[2*ni2+1][0], b[2*ni2+1][1],
                            stB + bOff[ni2] + kk * 2);
            #pragma unroll
            for (int mi = 0; mi < 2; mi++) {
                #pragma unroll
                for (int ni = 0; ni < 8; ni++) {
                    asm volatile(
                        "mma.sync.aligned.m16n8k16.row.col.f32.f16.f16.f32 "
                        "{%0,%1,%2,%3}, {%4,%5,%6,%7}, {%8,%9}, {%0,%1,%2,%3};"
                        : "+f"(acc[mi][ni][0]), "+f"(acc[mi][ni][1]),
                          "+f"(acc[mi][ni][2]), "+f"(acc[mi][ni][3])
                        : "r"(a[mi][0]), "r"(a[mi][1]),
                          "r"(a[mi][2]), "r"(a[mi][3]),
                          "r"(b[ni][0]), "r"(b[ni][1]));
                }
            }
        }
    }

    // -------- final epilogue --------
    #pragma unroll
    for (int mi = 0; mi < 2; mi++) {
        const int r0 = bm + wm * 32 + mi * 16 + lr;
        const int r1 = r0 + 8;
        #pragma unroll
        for (int ni = 0; ni < 8; ni++) {
            const int c = bn + wn * 64 + ni * 8 + lk * 2;
            float v0 = fmaxf(acc[mi][ni][0] + bz[ni].x, 0.0f);
            float v1 = fmaxf(acc[mi][ni][1] + bz[ni].y, 0.0f);
            float v2 = fmaxf(acc[mi][ni][2] + bz[ni].x, 0.0f);
            float v3 = fmaxf(acc[mi][ni][3] + bz[ni].y, 0.0f);
            if (outH) {
                *reinterpret_cast<__half2*>(&outH[(size_t)r0 * HID + c]) =
                    __floats2half2_rn(v0 * ZSCALE, v1 * ZSCALE);
                *reinterpret_cast<__half2*>(&outH[(size_t)r1 * HID + c]) =
                    __floats2half2_rn(v2 * ZSCALE, v3 * ZSCALE);
            } else {
                *reinterpret_cast<float2*>(&outF[(size_t)r0 * HID + c]) =
                    make_float2(v0, v1);
                *reinterpret_cast<float2*>(&outF[(size_t)r1 * HID + c]) =
                    make_float2(v2, v3);
            }
        }
    }
}

// ---------------- launch ----------------
extern "C" void kernel_launch(void* const* d_in, const int* in_sizes, int n_in,
                              void* d_out, int out_size) {
    const float* xc    = (const float*)d_in[0];
    const float* xf    = (const float*)d_in[1];
    const float* Wc_w  = (const float*)d_in[2];
    const float* Wc_b  = (const float*)d_in[3];
    const float* Wu_w  = (const float*)d_in[4];
    const float* Wu_b  = (const float*)d_in[5];
    const float* Wut_w = (const float*)d_in[6];
    const float* Wut_b = (const float*)d_in[7];
    const float* rawU  = (const float*)d_in[8];
    float* out = (float*)d_out;

    __half *gWcat, *gWut, *gU, *gXcat, *gzA, *gzB;
    float *gbias;
    cudaGetSymbolAddress((void**)&gWcat, g_Wcat);
    cudaGetSymbolAddress((void**)&gWut,  g_Wut);
    cudaGetSymbolAddress((void**)&gU,    g_U);
    cudaGetSymbolAddress((void**)&gbias, g_bias);
    cudaGetSymbolAddress((void**)&gXcat, g_Xcat);
    cudaGetSymbolAddress((void**)&gzA,   g_zA);
    cudaGetSymbolAddress((void**)&gzB,   g_zB);

    cudaFuncSetAttribute(icnn_layer_f16,
                         cudaFuncAttributeMaxDynamicSharedMemorySize, SMEM_BYTES);

    {
        const int totP = 3 * WSEG + USEG + L_LAYERS * HID;
        prep_weights_kernel<<<(totP + 255) / 256, 256>>>(Wc_w, Wu_w, Wut_w,
                                                         rawU, Wc_b, Wu_b);
        const int totX = MB * KCAT;
        xcat_kernel<<<(totX + 255) / 256, 256>>>(xc, xf);
    }

    dim3 grid(HID / BN, MB / BM);   // (8, 64)
    dim3 blk(NTHREADS);

    const __half* zprev = nullptr;
    __half* zbuf[2] = {gzA, gzB};

    for (int i = 0; i < L_LAYERS; ++i) {
        const bool last = (i == L_LAYERS - 1);
        icnn_layer_f16<<<grid, blk, SMEM_BYTES>>>(
            gXcat,
            gWut + (size_t)i * HID * NF,
            gWcat + (size_t)i * HID * KCAT,
            zprev,
            (i > 0) ? (gU + (size_t)(i - 1) * HID * HID) : nullptr,
            Wut_b + i * HID,
            gbias + i * HID,
            last ? out : nullptr,
            last ? nullptr : zbuf[i & 1]);
        zprev = zbuf[i & 1];
    }
}